// round 16
// baseline (speedup 1.0000x reference)
#include <cuda_runtime.h>
#include <math.h>
#include <stdint.h>

#define HW_    96
#define CIN_   64
#define COUT_  64
#define B_     4
#define T_     8
#define BT_    (B_*T_)
#define PLANE  (HW_*HW_)
#define TILE   32
#define CICH   8
#define NCHUNK 8           // K=64 per phase
#define HALO   34
#define SPITCH 36
#define INPLN  (4 + HALO*SPITCH)   // per-channel padded plane (floats)
#define NTHR   128
#define WTOT   8

// ---- persistent scratch (static device allocations only) ----
__device__ float g_h  [B_*COUT_*PLANE];
__device__ float g_rh [B_*COUT_*PLANE];
__device__ float g_z  [B_*COUT_*PLANE];
#define XSZ ((size_t)BT_*COUT_*PLANE)
__device__ float g_xacc[3*XSZ];        // conv-of-x (+bias) for r,z,h

typedef unsigned long long u64;

__device__ __forceinline__ u64 pack2(float lo, float hi) {
    u64 r; asm("mov.b64 %0, {%1, %2};" : "=l"(r) : "f"(lo), "f"(hi)); return r;
}
__device__ __forceinline__ void unpack2(u64 v, float &lo, float &hi) {
    asm("mov.b64 {%0, %1}, %2;" : "=f"(lo), "=f"(hi) : "l"(v));
}
__device__ __forceinline__ void fma2(u64 &d, u64 a, u64 b) {
    asm("fma.rn.f32x2 %0, %1, %2, %0;" : "+l"(d) : "l"(a), "l"(b));
}
__device__ __forceinline__ uint32_t s2u(const void* p) {
    return (uint32_t)__cvta_generic_to_shared(p);
}
__device__ __forceinline__ void cp4(uint32_t smem, const float* g, bool v) {
    asm volatile("cp.async.ca.shared.global [%0], [%1], 4, %2;"
                 :: "r"(smem), "l"(g), "r"(v ? 4u : 0u));
}
__device__ __forceinline__ void cp16(uint32_t smem, const float* g, bool v) {
    asm volatile("cp.async.cg.shared.global [%0], [%1], 16, %2;"
                 :: "r"(smem), "l"(g), "r"(v ? 16u : 0u));
}
#define CP_COMMIT() asm volatile("cp.async.commit_group;" ::: "memory")
#define CP_WAIT0()  asm volatile("cp.async.wait_group 0;"  ::: "memory")

struct SMData {
    float in[2][CICH][INPLN];          // per channel: pad(4) + 34 rows of 36
    u64   w [2][CICH][9][WTOT];        // tap-major: [ci][k][slot]
};

// ---------------------------------------------------------------------------
// K=64 conv over `src` (64ch image), 8 output-channel slots.
// 128 thr: tx=tid&7 (4-col group), ty=tid>>3 (2-row group). Warp fills 2 chans.
// Per ci: 12 input LDS + 36 weight LDS.128 feed 288 FFMA2 (6:1 FMA:LDS).
// acc[row(2)][pair(2)][slot(8)] packed pixel-pairs.
// ---------------------------------------------------------------------------
__device__ __forceinline__ void conv64(
    const float* __restrict__ src,
    const float* __restrict__ my_w, bool wact, int wci,
    int tile_x, int tile_y, int tid,
    u64 acc[2][2][WTOT])
{
    extern __shared__ char dynsmem[];
    SMData* sm = reinterpret_cast<SMData*>(dynsmem);

    const int tx   = tid & 7;
    const int ty   = tid >> 3;
    const int wid  = tid >> 5;
    const int lane = tid & 31;
    const int lx = tx * 4;
    const int ly = ty * 2;
    const int base_y = tile_y * TILE - 1;
    const int base_x = tile_x * TILE - 1;     // left halo gmem x
    const int main_x = base_x + 1;            // 16B-aligned gmem column

    auto loadw = [&](int c, float wreg[9]) {
        const float* wp = my_w + (size_t)(c * CICH + wci) * 9;
        #pragma unroll
        for (int k = 0; k < 9; k++) wreg[k] = wp[k];
    };
    auto stsw = [&](int c, const float wreg[9]) {
        int buf = c & 1;
        int wslot = wact ? (tid >> 3) : 0;
        #pragma unroll
        for (int k = 0; k < 9; k++)
            sm->w[buf][wci][k][wslot] = pack2(wreg[k], wreg[k]);
    };
    auto cpin = [&](int c) {
        int buf = c & 1;
        #pragma unroll
        for (int i = 0; i < 2; i++) {
            int ch = wid * 2 + i;
            const float* chp = src + (size_t)(c * CICH + ch) * PLANE;
            float* sbase = &sm->in[buf][ch][4];
            // mains: 34 rows x 8 segs of 16B = 272 ops across 32 lanes
            #pragma unroll
            for (int it = 0; it < 9; it++) {
                int idx = it * 32 + lane;
                if (idx < 272) {
                    int r = idx >> 3, seg = idx & 7;
                    int gy = base_y + r;
                    bool ok = (unsigned)gy < HW_;
                    cp16(s2u(sbase + r * SPITCH + seg * 4),
                         chp + gy * HW_ + main_x + seg * 4, ok);
                }
            }
            // edges: 34 rows x {left, right} = 68 ops
            #pragma unroll
            for (int it = 0; it < 3; it++) {
                int idx = it * 32 + lane;
                if (idx < 68) {
                    int r = idx >> 1, side = idx & 1;
                    int gy = base_y + r;
                    int gx = side ? (base_x + 33) : base_x;
                    bool ok = ((unsigned)gy < HW_) && ((unsigned)gx < HW_);
                    cp4(s2u(sbase + r * SPITCH + (side ? 32 : -1)),
                        chp + gy * HW_ + gx, ok);
                }
            }
        }
    };

    float wreg[9];
    if (wact) loadw(0, wreg);
    cpin(0);
    CP_COMMIT();
    if (wact) stsw(0, wreg);

    for (int c = 0; c < NCHUNK; c++) {
        const int buf = c & 1;
        const bool more = (c + 1) < NCHUNK;
        if (more && wact) loadw(c + 1, wreg);
        CP_WAIT0();
        __syncthreads();
        if (more) {
            cpin(c + 1);
            CP_COMMIT();
            if (wact) stsw(c + 1, wreg);
        }
        #pragma unroll
        for (int ci = 0; ci < CICH; ci++) {
            const float* dp = &sm->in[buf][ci][4] + ly * SPITCH + lx;
            u64 p[4][5];
            #pragma unroll
            for (int r = 0; r < 4; r++) {
                float  sl = dp[r * SPITCH - 1];
                float4 q  = *(const float4*)(dp + r * SPITCH);
                float  sr = dp[r * SPITCH + 4];
                p[r][0] = pack2(sl, q.x);
                p[r][1] = pack2(q.x, q.y);
                p[r][2] = pack2(q.y, q.z);
                p[r][3] = pack2(q.z, q.w);
                p[r][4] = pack2(q.w, sr);
            }
            const u64* wk = &sm->w[buf][ci][0][0];
            #pragma unroll
            for (int sp = 0; sp < WTOT / 2; sp++) {
                #pragma unroll
                for (int k = 0; k < 9; k++) {
                    int ky = k / 3, kx = k - ky * 3;
                    ulonglong2 w2 = *(const ulonglong2*)(wk + k * WTOT + sp * 2);
                    #pragma unroll
                    for (int r = 0; r < 2; r++) {
                        fma2(acc[r][0][2 * sp],     w2.x, p[r + ky][kx]);
                        fma2(acc[r][1][2 * sp],     w2.x, p[r + ky][kx + 2]);
                        fma2(acc[r][0][2 * sp + 1], w2.y, p[r + ky][kx]);
                        fma2(acc[r][1][2 * sp + 1], w2.y, p[r + ky][kx + 2]);
                    }
                }
            }
        }
    }
}

__device__ __forceinline__ float sigmoidf_(float v) {
    return 1.0f / (1.0f + __expf(-v));
}
__device__ __forceinline__ float tanhf_(float v) {
    return 2.0f / (1.0f + __expf(-2.0f * v)) - 1.0f;
}

// ===========================================================================
// Phase 1: precompute conv-of-x (+bias) for all (b,t), all 3 convs.
// grid (3,3,768): cog = bz&7, bt = (bz>>3)&31, conv = bz>>8
// ===========================================================================
__global__ void __launch_bounds__(NTHR, 2) xconv_kernel(
    const float* __restrict__ x,
    const float* __restrict__ w_r, const float* __restrict__ b_r,
    const float* __restrict__ w_z, const float* __restrict__ b_z,
    const float* __restrict__ w_h, const float* __restrict__ b_h)
{
    const int bz   = blockIdx.z;
    const int cog  = bz & 7;
    const int bt   = (bz >> 3) & 31;
    const int conv = bz >> 8;

    const float* wts  = (conv == 0) ? w_r : (conv == 1) ? w_z : w_h;
    const float* bias = (conv == 0) ? b_r : (conv == 1) ? b_z : b_h;
    const float* src  = x + (size_t)bt * CIN_ * PLANE;

    const int tid   = threadIdx.x;
    const int wci   = tid & 7;
    const int wslot = tid >> 3;
    const bool wact = (wslot < WTOT);
    const int my_co = cog * WTOT + (wact ? wslot : 0);
    const float* my_w = wts + (size_t)my_co * (CIN_ + COUT_) * 9;   // x-part

    u64 acc[2][2][WTOT];
    #pragma unroll
    for (int s = 0; s < WTOT; s++) {
        float bv = bias[cog * WTOT + s];
        u64 bp = pack2(bv, bv);
        acc[0][0][s] = bp; acc[0][1][s] = bp;
        acc[1][0][s] = bp; acc[1][1][s] = bp;
    }

    conv64(src, my_w, wact, wci, blockIdx.x, blockIdx.y, tid, acc);

    const int tx = tid & 7, ty = tid >> 3;
    const int gy0 = blockIdx.y * TILE + ty * 2;
    const int gx  = blockIdx.x * TILE + tx * 4;
    float* dst = g_xacc + (size_t)conv * XSZ;
    #pragma unroll
    for (int r = 0; r < 2; r++) {
        int gy = gy0 + r;
        #pragma unroll
        for (int s = 0; s < WTOT; s++) {
            int co = cog * WTOT + s;
            float v0, v1, v2, v3;
            unpack2(acc[r][0][s], v0, v1);
            unpack2(acc[r][1][s], v2, v3);
            *(float4*)(dst + ((size_t)(bt * COUT_ + co)) * PLANE + gy * HW_ + gx)
                = make_float4(v0, v1, v2, v3);
        }
    }
}

// ===========================================================================
// Phase 2a: gates. grid (3,3,64): cog = bz&7, b = (bz>>3)&3, gate = bz>>5
// gate 0 -> r (writes g_rh = sigmoid(r)*h), gate 1 -> z (writes g_z)
// ===========================================================================
__global__ void __launch_bounds__(NTHR, 2) gates_kernel(
    const float* __restrict__ w_r,
    const float* __restrict__ w_z,
    int t)
{
    const int bz   = blockIdx.z;
    const int cog  = bz & 7;
    const int b    = (bz >> 3) & 3;
    const int gate = bz >> 5;
    const int bt   = b * T_ + t;

    const float* src = g_h + (size_t)b * COUT_ * PLANE;

    const int tid   = threadIdx.x;
    const int wci   = tid & 7;
    const int wslot = tid >> 3;
    const bool wact = (wslot < WTOT);
    const int my_co = cog * WTOT + (wact ? wslot : 0);
    const float* wb = gate ? w_z : w_r;
    const float* my_w = wb + ((size_t)my_co * (CIN_ + COUT_) + CIN_) * 9;  // h-part

    const int tx = tid & 7, ty = tid >> 3;
    const int gy0 = blockIdx.y * TILE + ty * 2;
    const int gx  = blockIdx.x * TILE + tx * 4;

    // init acc from precomputed x-conv (+bias)
    u64 acc[2][2][WTOT];
    #pragma unroll
    for (int r = 0; r < 2; r++) {
        int gy = gy0 + r;
        #pragma unroll
        for (int s = 0; s < WTOT; s++) {
            int co = cog * WTOT + s;
            float4 q = *(const float4*)(g_xacc + (size_t)gate * XSZ +
                ((size_t)(bt * COUT_ + co)) * PLANE + gy * HW_ + gx);
            acc[r][0][s] = pack2(q.x, q.y);
            acc[r][1][s] = pack2(q.z, q.w);
        }
    }

    conv64(src, my_w, wact, wci, blockIdx.x, blockIdx.y, tid, acc);

    #pragma unroll
    for (int r = 0; r < 2; r++) {
        int gy = gy0 + r;
        #pragma unroll
        for (int s = 0; s < WTOT; s++) {
            int co = cog * WTOT + s;
            size_t idx = (size_t)(b * COUT_ + co) * PLANE + gy * HW_ + gx;
            float v0, v1, v2, v3;
            unpack2(acc[r][0][s], v0, v1);
            unpack2(acc[r][1][s], v2, v3);
            if (gate == 0) {
                float4 h = *(const float4*)(g_h + idx);
                *(float4*)(g_rh + idx) = make_float4(
                    sigmoidf_(v0) * h.x, sigmoidf_(v1) * h.y,
                    sigmoidf_(v2) * h.z, sigmoidf_(v3) * h.w);
            } else {
                *(float4*)(g_z + idx) = make_float4(
                    sigmoidf_(v0), sigmoidf_(v1),
                    sigmoidf_(v2), sigmoidf_(v3));
            }
        }
    }
}

// ===========================================================================
// Phase 2b: update. grid (3,3,32): cog = bz&7, b = bz>>3
// ===========================================================================
__global__ void __launch_bounds__(NTHR, 2) update_kernel(
    const float* __restrict__ w_h,
    float* __restrict__ out, int t)
{
    const int bz  = blockIdx.z;
    const int cog = bz & 7;
    const int b   = bz >> 3;
    const int bt  = b * T_ + t;

    const float* src = g_rh + (size_t)b * COUT_ * PLANE;

    const int tid   = threadIdx.x;
    const int wci   = tid & 7;
    const int wslot = tid >> 3;
    const bool wact = (wslot < WTOT);
    const int my_co = cog * WTOT + (wact ? wslot : 0);
    const float* my_w = w_h + ((size_t)my_co * (CIN_ + COUT_) + CIN_) * 9;

    const int tx = tid & 7, ty = tid >> 3;
    const int gy0 = blockIdx.y * TILE + ty * 2;
    const int gx  = blockIdx.x * TILE + tx * 4;

    u64 acc[2][2][WTOT];
    #pragma unroll
    for (int r = 0; r < 2; r++) {
        int gy = gy0 + r;
        #pragma unroll
        for (int s = 0; s < WTOT; s++) {
            int co = cog * WTOT + s;
            float4 q = *(const float4*)(g_xacc + 2 * XSZ +
                ((size_t)(bt * COUT_ + co)) * PLANE + gy * HW_ + gx);
            acc[r][0][s] = pack2(q.x, q.y);
            acc[r][1][s] = pack2(q.z, q.w);
        }
    }

    conv64(src, my_w, wact, wci, blockIdx.x, blockIdx.y, tid, acc);

    #pragma unroll
    for (int r = 0; r < 2; r++) {
        int gy = gy0 + r;
        #pragma unroll
        for (int s = 0; s < WTOT; s++) {
            int co = cog * WTOT + s;
            size_t idx  = (size_t)(b * COUT_ + co) * PLANE + gy * HW_ + gx;
            size_t oidx = (size_t)(bt * COUT_ + co) * PLANE + gy * HW_ + gx;
            float v0, v1, v2, v3;
            unpack2(acc[r][0][s], v0, v1);
            unpack2(acc[r][1][s], v2, v3);
            float4 z = *(const float4*)(g_z + idx);
            float4 h = *(const float4*)(g_h + idx);
            float4 hn;
            hn.x = h.x + z.x * (tanhf_(v0) - h.x);
            hn.y = h.y + z.y * (tanhf_(v1) - h.y);
            hn.z = h.z + z.z * (tanhf_(v2) - h.z);
            hn.w = h.w + z.w * (tanhf_(v3) - h.w);
            *(float4*)(g_h + idx)  = hn;
            *(float4*)(out + oidx) = hn;
        }
    }
}

__global__ void zero_h_kernel() {
    int i = blockIdx.x * 256 + threadIdx.x;
    if (i < B_ * COUT_ * PLANE) g_h[i] = 0.0f;
}

extern "C" void kernel_launch(void* const* d_in, const int* in_sizes, int n_in,
                              void* d_out, int out_size)
{
    const float* x   = (const float*)d_in[0];
    const float* w_r = (const float*)d_in[1];
    const float* b_r = (const float*)d_in[2];
    const float* w_z = (const float*)d_in[3];
    const float* b_z = (const float*)d_in[4];
    const float* w_h = (const float*)d_in[5];
    const float* b_h = (const float*)d_in[6];
    float* out = (float*)d_out;

    static bool attr_done = false;
    const int smem = (int)sizeof(SMData);
    if (!attr_done) {
        cudaFuncSetAttribute(xconv_kernel,
            cudaFuncAttributeMaxDynamicSharedMemorySize, smem);
        cudaFuncSetAttribute(gates_kernel,
            cudaFuncAttributeMaxDynamicSharedMemorySize, smem);
        cudaFuncSetAttribute(update_kernel,
            cudaFuncAttributeMaxDynamicSharedMemorySize, smem);
        attr_done = true;
    }

    zero_h_kernel<<<(B_ * COUT_ * PLANE + 255) / 256, 256>>>();

    dim3 xGrid(3, 3, 3 * BT_ * (COUT_ / WTOT));   // (3,3,768)
    xconv_kernel<<<xGrid, NTHR, smem>>>(x, w_r, b_r, w_z, b_z, w_h, b_h);

    dim3 gGrid(3, 3, 2 * B_ * (COUT_ / WTOT));    // (3,3,64)
    dim3 uGrid(3, 3, B_ * (COUT_ / WTOT));        // (3,3,32)
    for (int t = 0; t < T_; t++) {
        gates_kernel<<<gGrid, NTHR, smem>>>(w_r, w_z, t);
        update_kernel<<<uGrid, NTHR, smem>>>(w_h, out, t);
    }
}